// round 13
// baseline (speedup 1.0000x reference)
#include <cuda_runtime.h>
#include <cuda_fp16.h>
#include <cstdint>
#include <cmath>

#define T_SEQ 256
#define BATCH 64
#define EMB   512
#define HID   1024
#define GATES 4096   // 4*HID, gate order i,f,g,o

#define NCTA     128
#define NTHREADS 256

// ---- persistent-kernel smem layout (bytes) ----
#define SW_STRIDE 516                    // uint32 words per W row (staging only)
#define SA_STRIDE 132                    // uint32 words per A row per chunk
#define SA_BUF_W  (64 * SA_STRIDE)
#define GBUF_W    (64 * 33)              // one partial-accumulator buffer (words)
#define SMO_A     64                     // A buffers; W staged here pre-loop
#define SMO_GBUF  (SMO_A + 3 * SA_BUF_W * 4)             // 101440
#define SMEM_BYTES (SMO_GBUF + 8 * GBUF_W * 4)           // 169024

// ---------------- scratch (device globals) ---------------------------------
__device__ __align__(16) float  g_xgates[(size_t)T_SEQ * BATCH * GATES];
__device__ __align__(16) __half g_h[2][BATCH * HID];     // double-buffered
__device__ __align__(16) float  g_c[BATCH * HID];
__device__ unsigned g_bar;               // monotonic grid barrier

// ---------------- helpers ---------------------------------------------------
// fp16 m16n8k16, fp32 accum
__device__ __forceinline__ void mma_f16(float* d, const uint32_t* a, uint32_t b0, uint32_t b1) {
    asm volatile(
        "mma.sync.aligned.m16n8k16.row.col.f32.f16.f16.f32 "
        "{%0,%1,%2,%3}, {%4,%5,%6,%7}, {%8,%9}, {%0,%1,%2,%3};\n"
        : "+f"(d[0]), "+f"(d[1]), "+f"(d[2]), "+f"(d[3])
        : "r"(a[0]), "r"(a[1]), "r"(a[2]), "r"(a[3]),
          "r"(b0), "r"(b1));
}

__device__ __forceinline__ void ldsm_x4(uint32_t& r0, uint32_t& r1, uint32_t& r2,
                                        uint32_t& r3, uint32_t addr) {
    asm volatile("ldmatrix.sync.aligned.m8n8.x4.shared.b16 {%0,%1,%2,%3}, [%4];"
                 : "=r"(r0), "=r"(r1), "=r"(r2), "=r"(r3) : "r"(addr));
}

__device__ __forceinline__ void cp_async16(uint32_t saddr, const void* gaddr) {
    asm volatile("cp.async.cg.shared.global [%0], [%1], 16;\n" :: "r"(saddr), "l"(gaddr));
}
__device__ __forceinline__ void cp_commit() { asm volatile("cp.async.commit_group;\n"); }
__device__ __forceinline__ void cp_wait0()  { asm volatile("cp.async.wait_group 0;\n"); }
__device__ __forceinline__ void cp_wait1()  { asm volatile("cp.async.wait_group 1;\n"); }

__device__ __forceinline__ uint32_t smem_u32(const void* p) {
    return (uint32_t)__cvta_generic_to_shared(p);
}

__device__ __forceinline__ uint32_t pack_h2(float x, float y) {
    __half2 hv = __floats2half2_rn(x, y);
    return *(uint32_t*)&hv;
}

// fast gate functions (MUFU-based; err ~1e-6, negligible vs fp16 quantization)
__device__ __forceinline__ float fast_sigmoid(float x) {
    return __fdividef(1.0f, 1.0f + __expf(-x));
}
__device__ __forceinline__ float fast_tanh(float x) {
    return 1.0f - __fdividef(2.0f, __expf(2.0f * x) + 1.0f);
}

// ---------------- init: zero h0 ---------------------------------------------
__global__ void init_state() {
    int i = blockIdx.x * blockDim.x + threadIdx.x;
    if (i < BATCH * HID) g_h[0][i] = __float2half(0.0f);
}

// ---------------- input projection (fp16, 128x128 tile; unchanged) ----------
__global__ void __launch_bounds__(256)
input_gemm(const int* __restrict__ x_seq, const float* __restrict__ emb,
           const float* __restrict__ W_ih, const float* __restrict__ b_ih,
           const float* __restrict__ b_hh) {
    __shared__ uint32_t sA[128 * 20];
    __shared__ uint32_t sB[128 * 20];
    __shared__ int stok[128];

    const int tid = threadIdx.x;
    const int bm = blockIdx.y;
    const int bn = blockIdx.x;

    if (tid < 128) stok[tid] = x_seq[bm * 128 + tid];
    __syncthreads();

    const int lane = tid & 31;
    const int w    = tid >> 5;
    const int wm   = w & 3;
    const int wn   = w >> 2;
    const int grp  = lane >> 2;
    const int q4   = lane & 3;

    float acc[2][8][4];
    #pragma unroll
    for (int i = 0; i < 2; i++)
        #pragma unroll
        for (int j = 0; j < 8; j++)
            #pragma unroll
            for (int r = 0; r < 4; r++) acc[i][j][r] = 0.0f;

    float4 ra[4], rb[4];
    const int arow = tid >> 3;
    const int af4  = tid & 7;

    auto load_chunk = [&](int kb) {
        #pragma unroll
        for (int j = 0; j < 4; j++) {
            const int r = arow + j * 32;
            ra[j] = *(const float4*)(emb + (size_t)stok[r] * EMB + kb + af4 * 4);
            rb[j] = *(const float4*)(W_ih + (size_t)(bn * 128 + r) * EMB + kb + af4 * 4);
        }
    };
    auto store_chunk = [&]() {
        #pragma unroll
        for (int j = 0; j < 4; j++) {
            const int r = arow + j * 32;
            uint32_t* pa = sA + r * 20 + af4 * 2;
            pa[0] = pack_h2(ra[j].x, ra[j].y);
            pa[1] = pack_h2(ra[j].z, ra[j].w);
            uint32_t* pb = sB + r * 20 + af4 * 2;
            pb[0] = pack_h2(rb[j].x, rb[j].y);
            pb[1] = pack_h2(rb[j].z, rb[j].w);
        }
    };
    auto compute = [&]() {
        #pragma unroll
        for (int ks = 0; ks < 2; ks++) {
            const int k0 = ks * 8;
            uint32_t af[2][4];
            #pragma unroll
            for (int fm = 0; fm < 2; fm++) {
                const int r = wm * 32 + fm * 16 + grp;
                af[fm][0] = sA[r * 20 + k0 + q4];
                af[fm][1] = sA[(r + 8) * 20 + k0 + q4];
                af[fm][2] = sA[r * 20 + k0 + q4 + 4];
                af[fm][3] = sA[(r + 8) * 20 + k0 + q4 + 4];
            }
            #pragma unroll
            for (int fn = 0; fn < 8; fn++) {
                const int c = wn * 64 + fn * 8 + grp;
                const uint32_t b0 = sB[c * 20 + k0 + q4];
                const uint32_t b1 = sB[c * 20 + k0 + q4 + 4];
                #pragma unroll
                for (int fm = 0; fm < 2; fm++)
                    mma_f16(acc[fm][fn], af[fm], b0, b1);
            }
        }
    };

    load_chunk(0);
    store_chunk();
    __syncthreads();
    for (int kb = 0; kb < EMB; kb += 32) {
        const bool more = (kb + 32) < EMB;
        if (more) load_chunk(kb + 32);
        compute();
        __syncthreads();
        if (more) { store_chunk(); __syncthreads(); }
    }

    #pragma unroll
    for (int fm = 0; fm < 2; fm++)
        #pragma unroll
        for (int fn = 0; fn < 8; fn++) {
            const int row = bm * 128 + wm * 32 + fm * 16 + grp;
            const int col = bn * 128 + wn * 64 + fn * 8 + q4 * 2;
            const float bi0 = b_ih[col] + b_hh[col];
            const float bi1 = b_ih[col + 1] + b_hh[col + 1];
            float* o0 = g_xgates + (size_t)row * GATES + col;
            o0[0] = acc[fm][fn][0] + bi0;
            o0[1] = acc[fm][fn][1] + bi1;
            float* o1 = g_xgates + (size_t)(row + 8) * GATES + col;
            o1[0] = acc[fm][fn][2] + bi0;
            o1[1] = acc[fm][fn][3] + bi1;
        }
}

// ---------------- persistent recurrence -------------------------------------
// 8 warps, each owns a K-slice (k-steps 2w, 2w+1 of every chunk) and computes
// the FULL 64x32 output over its slice. W fragments live in REGISTERS for all
// 256 steps (zero W crossbar traffic). 8 partial buffers summed in epilogue.
// Park stores are SCALAR (stride 33 is odd -> float2 would misalign).
__global__ void __launch_bounds__(NTHREADS, 1)
lstm_persistent(const float* __restrict__ W_hh, float* __restrict__ out) {
    extern __shared__ char smem[];
    const uint32_t smb = smem_u32(smem);
    float* gbuf = (float*)(smem + SMO_GBUF);   // [8][64][33]

    const int tid  = threadIdx.x;
    const int hj   = blockIdx.x * 8;
    const int lane = tid & 31;
    const int w    = tid >> 5;
    const int grp  = lane >> 2;
    const int q4   = lane & 3;

    // ---- one-time: stage W (32 x 1024 fp16) into smem (A-buffer region) ----
    {
        uint32_t* sW = (uint32_t*)(smem + SMO_A);
        for (int it = tid; it < 32 * 512; it += NTHREADS) {
            const int n  = it >> 9;
            const int w2 = it & 511;
            const float2 v = *(const float2*)(
                W_hh + (size_t)((n >> 3) * HID + hj + (n & 7)) * HID + w2 * 2);
            sW[n * SW_STRIDE + w2] = pack_h2(v.x, v.y);
        }
    }
    __syncthreads();

    // ---- one-time: W fragments -> registers (8 k-steps x 4 n-frags) ----
    // slot s = c*2 + j covers global k-step ksl_g = c*16 + 2w + j
    uint32_t wr[8][8];
    {
        const uint32_t wAddr0 = smb + SMO_A +
            ((uint32_t)(lane & 15) * SW_STRIDE + ((lane >> 4) << 2)) * 4;
        const uint32_t wAddr1 = wAddr0 + 16 * SW_STRIDE * 4;
        #pragma unroll
        for (int c = 0; c < 4; c++)
            #pragma unroll
            for (int j = 0; j < 2; j++) {
                const int s = c * 2 + j;
                const uint32_t kB = (uint32_t)(c * 16 + 2 * w + j) * 32;
                ldsm_x4(wr[s][0], wr[s][1], wr[s][2], wr[s][3], wAddr0 + kB);
                ldsm_x4(wr[s][4], wr[s][5], wr[s][6], wr[s][7], wAddr1 + kB);
            }
    }
    __syncthreads();   // all warps done reading W staging before A fills reuse it

    // A ldmatrix lane base: row (lane&15), k-word group (lane>>4)*4
    const uint32_t aAddrL = smb + SMO_A +
        ((uint32_t)(lane & 15) * SA_STRIDE + ((lane >> 4) << 2)) * 4;
    const uint32_t A_MF = 16 * SA_STRIDE * 4;     // +16 rows per m-frag
    const uint32_t kslB = (uint32_t)(2 * w) * 32; // this warp's k-byte base per chunk

    auto fill = [&](const __half* h_in, int c) {
        const int buf = c % 3;
        #pragma unroll
        for (int j = 0; j < 8; j++) {
            const int gi = tid + j * NTHREADS;
            const int b  = gi >> 5;
            const int g  = gi & 31;
            cp_async16(smb + SMO_A + (buf * SA_BUF_W + b * SA_STRIDE + g * 4) * 4,
                       h_in + (size_t)b * HID + c * 256 + g * 8);
        }
        cp_commit();
    };

    // epilogue item indices (fixed per thread)
    const int eb0 = tid >> 3,               ehh0 = tid & 7;
    const int eb1 = (tid + NTHREADS) >> 3,  ehh1 = (tid + NTHREADS) & 7;

    float creg[2] = {0.f, 0.f};            // cell state lives in registers
    float* gbw = gbuf + w * GBUF_W;        // this warp's partial buffer

    for (int t = 0; t < T_SEQ; t++) {
        const __half* __restrict__ h_in  = g_h[t & 1];
        __half* __restrict__       h_out = g_h[(t + 1) & 1];

        float acc[4][4][4];                // [m-frag][n-frag][regs]
        #pragma unroll
        for (int i = 0; i < 4; i++)
            #pragma unroll
            for (int j = 0; j < 4; j++)
                #pragma unroll
                for (int r = 0; r < 4; r++) acc[i][j][r] = 0.0f;

        fill(h_in, 0);

        // prefetch xgates for this step's epilogue (hide DRAM/L2 latency)
        float xg0[4], xg1[4];
        {
            const float* p0 = g_xgates + ((size_t)t * BATCH + eb0) * GATES + hj + ehh0;
            const float* p1 = g_xgates + ((size_t)t * BATCH + eb1) * GATES + hj + ehh1;
            #pragma unroll
            for (int g = 0; g < 4; g++) {
                xg0[g] = __ldg(p0 + g * HID);
                xg1[g] = __ldg(p1 + g * HID);
            }
        }

        #pragma unroll
        for (int c = 0; c < 4; c++) {
            if (c < 3) { fill(h_in, c + 1); cp_wait1(); }
            else       { cp_wait0(); }
            __syncthreads();

            const uint32_t aBase = aAddrL + (uint32_t)(c % 3) * (SA_BUF_W * 4) + kslB;
            #pragma unroll
            for (int j = 0; j < 2; j++) {
                const int s = c * 2 + j;
                const uint32_t kB = (uint32_t)j * 32;
                #pragma unroll
                for (int mf = 0; mf < 4; mf++) {
                    uint32_t a[4];
                    ldsm_x4(a[0], a[1], a[2], a[3], aBase + (uint32_t)mf * A_MF + kB);
                    mma_f16(acc[mf][0], a, wr[s][0], wr[s][2]);
                    mma_f16(acc[mf][1], a, wr[s][1], wr[s][3]);
                    mma_f16(acc[mf][2], a, wr[s][4], wr[s][6]);
                    mma_f16(acc[mf][3], a, wr[s][5], wr[s][7]);
                }
            }
        }

        // park this warp's full 64x32 partial into its own buffer (scalar stores)
        #pragma unroll
        for (int mf = 0; mf < 4; mf++) {
            const int row = mf * 16 + grp;
            #pragma unroll
            for (int fn = 0; fn < 4; fn++) {
                const int col = fn * 8 + q4 * 2;
                gbw[row * 33 + col]           = acc[mf][fn][0];
                gbw[row * 33 + col + 1]       = acc[mf][fn][1];
                gbw[(row + 8) * 33 + col]     = acc[mf][fn][2];
                gbw[(row + 8) * 33 + col + 1] = acc[mf][fn][3];
            }
        }
        __syncthreads();

        // fused elementwise: sum the 8 K-slice partials + xg (pairwise)
        float hnew[2];
        #pragma unroll
        for (int it2 = 0; it2 < 2; it2++) {
            const int b    = it2 ? eb1 : eb0;
            const int hh   = it2 ? ehh1 : ehh0;
            const float* xg = it2 ? xg1 : xg0;
            const int hcol = hj + hh;

            float gp4[4];
            #pragma unroll
            for (int g = 0; g < 4; g++) {
                const int o = b * 33 + g * 8 + hh;
                float s01 = gbuf[o] + gbuf[GBUF_W + o];
                float s23 = gbuf[2 * GBUF_W + o] + gbuf[3 * GBUF_W + o];
                float s45 = gbuf[4 * GBUF_W + o] + gbuf[5 * GBUF_W + o];
                float s67 = gbuf[6 * GBUF_W + o] + gbuf[7 * GBUF_W + o];
                gp4[g] = ((s01 + s23) + (s45 + s67)) + xg[g];
            }

            const float ig = fast_sigmoid(gp4[0]);
            const float fg = fast_sigmoid(gp4[1]);
            const float gg = fast_tanh(gp4[2]);
            const float og = fast_sigmoid(gp4[3]);

            const float c_new = fg * creg[it2] + ig * gg;
            const float h_new = og * fast_tanh(c_new);
            creg[it2] = c_new;
            hnew[it2] = h_new;

            h_out[b * HID + hcol] = __float2half_rn(h_new);
        }

        // ---- grid barrier: single atomic, release early, overlap stores ----
        __syncthreads();                    // all h_out stores done
        unsigned target = 0;
        if (tid == 0) {
            __threadfence();
            unsigned old;
            asm volatile("atom.add.release.gpu.global.u32 %0, [%1], 1;"
                         : "=r"(old) : "l"(&g_bar) : "memory");
            target = old - (old % NCTA) + NCTA;
        }
        // fp32 output stores overlap the barrier poll below
        out[((size_t)t * BATCH + eb0) * HID + hj + ehh0] = hnew[0];
        out[((size_t)t * BATCH + eb1) * HID + hj + ehh1] = hnew[1];
        if (tid == 0) {
            unsigned cur;
            do {
                asm volatile("ld.acquire.gpu.global.u32 %0, [%1];"
                             : "=r"(cur) : "l"(&g_bar) : "memory");
            } while ((int)(cur - target) < 0);
        }
        __syncthreads();
    }

    // final cell state -> global (finalize reads it)
    g_c[eb0 * HID + hj + ehh0] = creg[0];
    g_c[eb1 * HID + hj + ehh1] = creg[1];
}

// ---------------- finalize: append (h, c) after outs ------------------------
__global__ void finalize(float* __restrict__ out) {
    int i = blockIdx.x * blockDim.x + threadIdx.x;
    if (i < BATCH * HID) {
        out[(size_t)T_SEQ * BATCH * HID + i] =
            out[(size_t)(T_SEQ - 1) * BATCH * HID + i];
        out[(size_t)T_SEQ * BATCH * HID + BATCH * HID + i] = g_c[i];
    }
}

// ---------------- launch -----------------------------------------------------
extern "C" void kernel_launch(void* const* d_in, const int* in_sizes, int n_in,
                              void* d_out, int out_size) {
    const int*   x_seq = (const int*)d_in[0];
    const float* emb   = (const float*)d_in[1];
    const float* W_ih  = (const float*)d_in[2];
    const float* W_hh  = (const float*)d_in[3];
    const float* b_ih  = (const float*)d_in[4];
    const float* b_hh  = (const float*)d_in[5];
    float* out = (float*)d_out;

    cudaFuncSetAttribute(lstm_persistent,
                         cudaFuncAttributeMaxDynamicSharedMemorySize, SMEM_BYTES);

    init_state<<<(BATCH * HID + 255) / 256, 256>>>();

    dim3 ig_grid(GATES / 128, (T_SEQ * BATCH) / 128);   // (32, 128)
    input_gemm<<<ig_grid, 256>>>(x_seq, emb, W_ih, b_ih, b_hh);

    lstm_persistent<<<NCTA, NTHREADS, SMEM_BYTES>>>(W_hh, out);

    finalize<<<(BATCH * HID + 255) / 256, 256>>>(out);
}

// round 15
// speedup vs baseline: 1.1178x; 1.1178x over previous
#include <cuda_runtime.h>
#include <cuda_fp16.h>
#include <cstdint>
#include <cmath>

#define T_SEQ 256
#define BATCH 64
#define EMB   512
#define HID   1024
#define GATES 4096   // 4*HID, gate order i,f,g,o
#define VOCAB 32000

#define NCTA     128
#define NTHREADS 256

// ---- persistent-kernel smem layout (R10, unchanged) ----
#define SW_STRIDE 516                    // uint32 words per W row (1032 halfs)
#define SA_STRIDE 132                    // uint32 words per A row per chunk
#define SA_BUF_W  (64 * SA_STRIDE)
#define GBUF_W    (64 * 33)
#define SMO_W     64
#define SMO_A     (SMO_W + 32 * SW_STRIDE * 4)
#define SMO_GBUF  (SMO_A + 3 * SA_BUF_W * 4)
#define SMEM_BYTES (SMO_GBUF + 2 * GBUF_W * 4)           // 184384

// ---------------- scratch (device globals) ---------------------------------
__device__ __align__(16) float  g_xgates[(size_t)T_SEQ * BATCH * GATES];
__device__ __align__(16) __half g_h[2][BATCH * HID];     // double-buffered
__device__ __align__(16) float  g_c[BATCH * HID];
__device__ __align__(16) __half g_emb_h[(size_t)VOCAB * EMB];   // fp16 emb (32 MB)
__device__ __align__(16) __half g_wih_h[(size_t)GATES * EMB];   // fp16 W_ih (4 MB)
__device__ unsigned g_bar;               // monotonic grid barrier

// ---------------- helpers ---------------------------------------------------
// fp16 m16n8k16, fp32 accum
__device__ __forceinline__ void mma_f16(float* d, const uint32_t* a, uint32_t b0, uint32_t b1) {
    asm volatile(
        "mma.sync.aligned.m16n8k16.row.col.f32.f16.f16.f32 "
        "{%0,%1,%2,%3}, {%4,%5,%6,%7}, {%8,%9}, {%0,%1,%2,%3};\n"
        : "+f"(d[0]), "+f"(d[1]), "+f"(d[2]), "+f"(d[3])
        : "r"(a[0]), "r"(a[1]), "r"(a[2]), "r"(a[3]),
          "r"(b0), "r"(b1));
}

__device__ __forceinline__ void ldsm_x4(uint32_t& r0, uint32_t& r1, uint32_t& r2,
                                        uint32_t& r3, uint32_t addr) {
    asm volatile("ldmatrix.sync.aligned.m8n8.x4.shared.b16 {%0,%1,%2,%3}, [%4];"
                 : "=r"(r0), "=r"(r1), "=r"(r2), "=r"(r3) : "r"(addr));
}

__device__ __forceinline__ void cp_async16(uint32_t saddr, const void* gaddr) {
    asm volatile("cp.async.cg.shared.global [%0], [%1], 16;\n" :: "r"(saddr), "l"(gaddr));
}
__device__ __forceinline__ void cp_commit() { asm volatile("cp.async.commit_group;\n"); }
__device__ __forceinline__ void cp_wait0()  { asm volatile("cp.async.wait_group 0;\n"); }
__device__ __forceinline__ void cp_wait1()  { asm volatile("cp.async.wait_group 1;\n"); }

__device__ __forceinline__ uint32_t smem_u32(const void* p) {
    return (uint32_t)__cvta_generic_to_shared(p);
}

__device__ __forceinline__ uint32_t pack_h2(float x, float y) {
    __half2 hv = __floats2half2_rn(x, y);
    return *(uint32_t*)&hv;
}

// fast gate functions (MUFU-based; err ~1e-6, negligible vs fp16 quantization)
__device__ __forceinline__ float fast_sigmoid(float x) {
    return __fdividef(1.0f, 1.0f + __expf(-x));
}
__device__ __forceinline__ float fast_tanh(float x) {
    return 1.0f - __fdividef(2.0f, __expf(2.0f * x) + 1.0f);
}

// ---------------- init: zero h0 ---------------------------------------------
__global__ void init_state() {
    int i = blockIdx.x * blockDim.x + threadIdx.x;
    if (i < BATCH * HID) g_h[0][i] = __float2half(0.0f);
}

// ---------------- fp32 -> fp16 pre-conversion (once per run) ----------------
__global__ void conv_emb(const float* __restrict__ src) {
    const size_t i = (size_t)blockIdx.x * blockDim.x + threadIdx.x;
    if (i < (size_t)VOCAB * EMB / 8) {
        const float4 a = ((const float4*)src)[2 * i];
        const float4 b = ((const float4*)src)[2 * i + 1];
        uint4 o;
        o.x = pack_h2(a.x, a.y); o.y = pack_h2(a.z, a.w);
        o.z = pack_h2(b.x, b.y); o.w = pack_h2(b.z, b.w);
        ((uint4*)g_emb_h)[i] = o;
    }
}

__global__ void conv_wih(const float* __restrict__ src) {
    const size_t i = (size_t)blockIdx.x * blockDim.x + threadIdx.x;
    if (i < (size_t)GATES * EMB / 8) {
        const float4 a = ((const float4*)src)[2 * i];
        const float4 b = ((const float4*)src)[2 * i + 1];
        uint4 o;
        o.x = pack_h2(a.x, a.y); o.y = pack_h2(a.z, a.w);
        o.z = pack_h2(b.x, b.y); o.w = pack_h2(b.z, b.w);
        ((uint4*)g_wih_h)[i] = o;
    }
}

// ---------------- input projection (fp16 inputs, 128x128 tile) --------------
// Tiles load directly from pre-converted fp16 (half the L2 traffic).
// Per K-chunk (32 halfs/row): 4 uint4 segments/row, 2 threads/row ->
// 2 uint4 per thread per tile.
__global__ void __launch_bounds__(256)
input_gemm(const int* __restrict__ x_seq, const float* __restrict__ b_ih,
           const float* __restrict__ b_hh) {
    __shared__ __align__(16) uint32_t sA[128 * 20];
    __shared__ __align__(16) uint32_t sB[128 * 20];
    __shared__ int stok[128];

    const int tid = threadIdx.x;
    const int bm = blockIdx.y;
    const int bn = blockIdx.x;

    if (tid < 128) stok[tid] = x_seq[bm * 128 + tid];
    __syncthreads();

    const int lane = tid & 31;
    const int w    = tid >> 5;
    const int wm   = w & 3;
    const int wn   = w >> 2;
    const int grp  = lane >> 2;
    const int q4   = lane & 3;

    float acc[2][8][4];
    #pragma unroll
    for (int i = 0; i < 2; i++)
        #pragma unroll
        for (int j = 0; j < 8; j++)
            #pragma unroll
            for (int r = 0; r < 4; r++) acc[i][j][r] = 0.0f;

    // staging: 2 uint4 (16 halfs) per thread per tile per K-chunk (32 halfs/row)
    uint4 ra[2], rb[2];
    const int trow = tid >> 1;          // tile row 0..127
    const int seg0 = (tid & 1) * 2;     // segments seg0, seg0+1 (of 4 per row)

    auto load_chunk = [&](int kb) {
        #pragma unroll
        for (int j = 0; j < 2; j++) {
            ra[j] = *(const uint4*)(g_emb_h + (size_t)stok[trow] * EMB + kb + (seg0 + j) * 8);
            rb[j] = *(const uint4*)(g_wih_h + (size_t)(bn * 128 + trow) * EMB + kb + (seg0 + j) * 8);
        }
    };
    auto store_chunk = [&]() {
        #pragma unroll
        for (int j = 0; j < 2; j++) {
            *(uint4*)(sA + trow * 20 + (seg0 + j) * 4) = ra[j];
            *(uint4*)(sB + trow * 20 + (seg0 + j) * 4) = rb[j];
        }
    };
    auto compute = [&]() {
        #pragma unroll
        for (int ks = 0; ks < 2; ks++) {
            const int k0 = ks * 8;
            uint32_t af[2][4];
            #pragma unroll
            for (int fm = 0; fm < 2; fm++) {
                const int r = wm * 32 + fm * 16 + grp;
                af[fm][0] = sA[r * 20 + k0 + q4];
                af[fm][1] = sA[(r + 8) * 20 + k0 + q4];
                af[fm][2] = sA[r * 20 + k0 + q4 + 4];
                af[fm][3] = sA[(r + 8) * 20 + k0 + q4 + 4];
            }
            #pragma unroll
            for (int fn = 0; fn < 8; fn++) {
                const int c = wn * 64 + fn * 8 + grp;
                const uint32_t b0 = sB[c * 20 + k0 + q4];
                const uint32_t b1 = sB[c * 20 + k0 + q4 + 4];
                #pragma unroll
                for (int fm = 0; fm < 2; fm++)
                    mma_f16(acc[fm][fn], af[fm], b0, b1);
            }
        }
    };

    load_chunk(0);
    store_chunk();
    __syncthreads();
    for (int kb = 0; kb < EMB; kb += 32) {
        const bool more = (kb + 32) < EMB;
        if (more) load_chunk(kb + 32);
        compute();
        __syncthreads();
        if (more) { store_chunk(); __syncthreads(); }
    }

    #pragma unroll
    for (int fm = 0; fm < 2; fm++)
        #pragma unroll
        for (int fn = 0; fn < 8; fn++) {
            const int row = bm * 128 + wm * 32 + fm * 16 + grp;
            const int col = bn * 128 + wn * 64 + fn * 8 + q4 * 2;
            const float bi0 = b_ih[col] + b_hh[col];
            const float bi1 = b_ih[col + 1] + b_hh[col + 1];
            float* o0 = g_xgates + (size_t)row * GATES + col;
            o0[0] = acc[fm][fn][0] + bi0;
            o0[1] = acc[fm][fn][1] + bi1;
            float* o1 = g_xgates + (size_t)(row + 8) * GATES + col;
            o1[0] = acc[fm][fn][2] + bi0;
            o1[1] = acc[fm][fn][3] + bi1;
        }
}

// ---------------- persistent recurrence (R10, byte-identical) ---------------
// 8 warps = 4 wm (16 M-rows) x 2 kh (even/odd k-steps). Fragments via
// ldmatrix.x4. Single-atomic monolithic grid barrier.
__global__ void __launch_bounds__(NTHREADS, 1)
lstm_persistent(const float* __restrict__ W_hh, float* __restrict__ out) {
    extern __shared__ char smem[];
    const uint32_t smb = smem_u32(smem);
    uint32_t* sW   = (uint32_t*)(smem + SMO_W);
    float*    gbuf = (float*)(smem + SMO_GBUF);   // [2][64][33]

    const int tid  = threadIdx.x;
    const int hj   = blockIdx.x * 8;
    const int lane = tid & 31;
    const int w    = tid >> 5;
    const int wm   = w & 3;          // m base wm*16
    const int kh   = w >> 2;         // K-half: even(0)/odd(1) k-steps
    const int grp  = lane >> 2;
    const int q4   = lane & 3;

    // ---- one-time: W slice (32 x 1024) -> smem fp16 ----
    for (int it = tid; it < 32 * 512; it += NTHREADS) {
        const int n  = it >> 9;
        const int w2 = it & 511;
        const float2 v = *(const float2*)(
            W_hh + (size_t)((n >> 3) * HID + hj + (n & 7)) * HID + w2 * 2);
        sW[n * SW_STRIDE + w2] = pack_h2(v.x, v.y);
    }
    __syncthreads();

    // ldmatrix lane base addresses (bytes)
    const uint32_t aAddrL = smb + SMO_A +
        ((uint32_t)(wm * 16 + (lane & 15)) * SA_STRIDE + ((lane >> 4) << 2)) * 4;
    const uint32_t wAddr0 = smb + SMO_W +
        ((uint32_t)(lane & 15) * SW_STRIDE + ((lane >> 4) << 2)) * 4;
    const uint32_t wAddr1 = wAddr0 + 16 * SW_STRIDE * 4;

    auto fill = [&](const __half* h_in, int c) {
        const int buf = c % 3;
        #pragma unroll
        for (int j = 0; j < 8; j++) {
            const int gi = tid + j * NTHREADS;
            const int b  = gi >> 5;
            const int g  = gi & 31;
            cp_async16(smb + SMO_A + (buf * SA_BUF_W + b * SA_STRIDE + g * 4) * 4,
                       h_in + (size_t)b * HID + c * 256 + g * 8);
        }
        cp_commit();
    };

    // epilogue item indices (fixed per thread)
    const int eb0 = tid >> 3,               ehh0 = tid & 7;
    const int eb1 = (tid + NTHREADS) >> 3,  ehh1 = (tid + NTHREADS) & 7;

    float creg[2] = {0.f, 0.f};            // cell state lives in registers

    for (int t = 0; t < T_SEQ; t++) {
        const __half* __restrict__ h_in  = g_h[t & 1];
        __half* __restrict__       h_out = g_h[(t + 1) & 1];

        float acc[4][4];
        #pragma unroll
        for (int i = 0; i < 4; i++)
            #pragma unroll
            for (int r = 0; r < 4; r++) acc[i][r] = 0.0f;

        fill(h_in, 0);

        // prefetch xgates for this step's epilogue (hide DRAM/L2 latency)
        float xg0[4], xg1[4];
        {
            const float* p0 = g_xgates + ((size_t)t * BATCH + eb0) * GATES + hj + ehh0;
            const float* p1 = g_xgates + ((size_t)t * BATCH + eb1) * GATES + hj + ehh1;
            #pragma unroll
            for (int g = 0; g < 4; g++) {
                xg0[g] = __ldg(p0 + g * HID);
                xg1[g] = __ldg(p1 + g * HID);
            }
        }

        #pragma unroll
        for (int c = 0; c < 4; c++) {
            if (c < 3) { fill(h_in, c + 1); cp_wait1(); }
            else       { cp_wait0(); }
            __syncthreads();

            const uint32_t aBase = aAddrL + (uint32_t)(c % 3) * (SA_BUF_W * 4);
            const uint32_t wOff  = (uint32_t)(c * 16) * 32;   // kw bytes
            #pragma unroll
            for (int ksl2 = 0; ksl2 < 8; ksl2++) {
                const int ksl = ksl2 * 2 + kh;       // interleaved K split
                uint32_t af[4];
                ldsm_x4(af[0], af[1], af[2], af[3], aBase + (uint32_t)ksl * 32);
                uint32_t w00, w01, w02, w03;
                ldsm_x4(w00, w01, w02, w03, wAddr0 + wOff + (uint32_t)ksl * 32);
                mma_f16(acc[0], af, w00, w02);
                mma_f16(acc[1], af, w01, w03);
                uint32_t w10, w11, w12, w13;
                ldsm_x4(w10, w11, w12, w13, wAddr1 + wOff + (uint32_t)ksl * 32);
                mma_f16(acc[2], af, w10, w12);
                mma_f16(acc[3], af, w11, w13);
            }
        }

        // park partial accumulators (per K-half)
        {
            float* gb = gbuf + kh * GBUF_W;
            const int row = wm * 16 + grp;
            #pragma unroll
            for (int fn = 0; fn < 4; fn++) {
                const int col = fn * 8 + q4 * 2;
                gb[row * 33 + col]           = acc[fn][0];
                gb[row * 33 + col + 1]       = acc[fn][1];
                gb[(row + 8) * 33 + col]     = acc[fn][2];
                gb[(row + 8) * 33 + col + 1] = acc[fn][3];
            }
        }
        __syncthreads();

        // fused elementwise: sum the two K-half partials + xg
        float hnew[2];
        #pragma unroll
        for (int it2 = 0; it2 < 2; it2++) {
            const int b    = it2 ? eb1 : eb0;
            const int hh   = it2 ? ehh1 : ehh0;
            const float* xg = it2 ? xg1 : xg0;
            const int hcol = hj + hh;

            const float ip = gbuf[b * 33 + hh]      + gbuf[GBUF_W + b * 33 + hh]      + xg[0];
            const float fp = gbuf[b * 33 + 8 + hh]  + gbuf[GBUF_W + b * 33 + 8 + hh]  + xg[1];
            const float gp = gbuf[b * 33 + 16 + hh] + gbuf[GBUF_W + b * 33 + 16 + hh] + xg[2];
            const float op = gbuf[b * 33 + 24 + hh] + gbuf[GBUF_W + b * 33 + 24 + hh] + xg[3];

            const float ig = fast_sigmoid(ip);
            const float fg = fast_sigmoid(fp);
            const float gg = fast_tanh(gp);
            const float og = fast_sigmoid(op);

            const float c_new = fg * creg[it2] + ig * gg;
            const float h_new = og * fast_tanh(c_new);
            creg[it2] = c_new;
            hnew[it2] = h_new;

            h_out[b * HID + hcol] = __float2half_rn(h_new);
        }

        // ---- grid barrier: single atomic, release early, overlap stores ----
        __syncthreads();                    // all h_out stores done
        unsigned target = 0;
        if (tid == 0) {
            __threadfence();
            unsigned old;
            asm volatile("atom.add.release.gpu.global.u32 %0, [%1], 1;"
                         : "=r"(old) : "l"(&g_bar) : "memory");
            target = old - (old % NCTA) + NCTA;
        }
        // fp32 output stores overlap the barrier poll below
        out[((size_t)t * BATCH + eb0) * HID + hj + ehh0] = hnew[0];
        out[((size_t)t * BATCH + eb1) * HID + hj + ehh1] = hnew[1];
        if (tid == 0) {
            unsigned cur;
            do {
                asm volatile("ld.acquire.gpu.global.u32 %0, [%1];"
                             : "=r"(cur) : "l"(&g_bar) : "memory");
            } while ((int)(cur - target) < 0);
        }
        __syncthreads();
    }

    // final cell state -> global (finalize reads it)
    g_c[eb0 * HID + hj + ehh0] = creg[0];
    g_c[eb1 * HID + hj + ehh1] = creg[1];
}

// ---------------- finalize: append (h, c) after outs ------------------------
__global__ void finalize(float* __restrict__ out) {
    int i = blockIdx.x * blockDim.x + threadIdx.x;
    if (i < BATCH * HID) {
        out[(size_t)T_SEQ * BATCH * HID + i] =
            out[(size_t)(T_SEQ - 1) * BATCH * HID + i];
        out[(size_t)T_SEQ * BATCH * HID + BATCH * HID + i] = g_c[i];
    }
}

// ---------------- launch -----------------------------------------------------
extern "C" void kernel_launch(void* const* d_in, const int* in_sizes, int n_in,
                              void* d_out, int out_size) {
    const int*   x_seq = (const int*)d_in[0];
    const float* emb   = (const float*)d_in[1];
    const float* W_ih  = (const float*)d_in[2];
    const float* W_hh  = (const float*)d_in[3];
    const float* b_ih  = (const float*)d_in[4];
    const float* b_hh  = (const float*)d_in[5];
    float* out = (float*)d_out;

    cudaFuncSetAttribute(lstm_persistent,
                         cudaFuncAttributeMaxDynamicSharedMemorySize, SMEM_BYTES);

    init_state<<<(BATCH * HID + 255) / 256, 256>>>();

    conv_emb<<<(int)(((size_t)VOCAB * EMB / 8 + 255) / 256), 256>>>(emb);
    conv_wih<<<(int)(((size_t)GATES * EMB / 8 + 255) / 256), 256>>>(W_ih);

    dim3 ig_grid(GATES / 128, (T_SEQ * BATCH) / 128);   // (32, 128)
    input_gemm<<<ig_grid, 256>>>(x_seq, b_ih, b_hh);

    lstm_persistent<<<NCTA, NTHREADS, SMEM_BYTES>>>(W_hh, out);

    finalize<<<(BATCH * HID + 255) / 256, 256>>>(out);
}

// round 16
// speedup vs baseline: 1.2107x; 1.0831x over previous
#include <cuda_runtime.h>
#include <cuda_fp16.h>
#include <cstdint>
#include <cmath>

#define T_SEQ 256
#define BATCH 64
#define EMB   512
#define HID   1024
#define GATES 4096   // 4*HID, gate order i,f,g,o
#define VOCAB 32000

#define NCTA     128
#define NTHREADS 256

// ---- persistent-kernel smem layout (R10, unchanged) ----
#define SW_STRIDE 516                    // uint32 words per W row (1032 halfs)
#define SA_STRIDE 132                    // uint32 words per A row per chunk
#define SA_BUF_W  (64 * SA_STRIDE)
#define GBUF_W    (64 * 33)
#define SMO_W     64
#define SMO_A     (SMO_W + 32 * SW_STRIDE * 4)
#define SMO_GBUF  (SMO_A + 3 * SA_BUF_W * 4)
#define SMEM_BYTES (SMO_GBUF + 2 * GBUF_W * 4)           // 184384

// ---- input_gemm tile constants ----
#define IG_STRIDE 20                     // words per tile row (16 + 4 pad)
#define IG_TILE_W (128 * IG_STRIDE)      // words per tile buffer

// ---------------- scratch (device globals) ---------------------------------
__device__ __align__(16) float  g_xgates[(size_t)T_SEQ * BATCH * GATES];
__device__ __align__(16) __half g_h[2][BATCH * HID];     // double-buffered
__device__ __align__(16) float  g_c[BATCH * HID];
__device__ __align__(16) __half g_emb_h[(size_t)VOCAB * EMB];   // fp16 emb (32 MB)
__device__ __align__(16) __half g_wih_h[(size_t)GATES * EMB];   // fp16 W_ih (4 MB)
__device__ unsigned g_bar;               // monotonic grid barrier

// ---------------- helpers ---------------------------------------------------
// fp16 m16n8k16, fp32 accum
__device__ __forceinline__ void mma_f16(float* d, const uint32_t* a, uint32_t b0, uint32_t b1) {
    asm volatile(
        "mma.sync.aligned.m16n8k16.row.col.f32.f16.f16.f32 "
        "{%0,%1,%2,%3}, {%4,%5,%6,%7}, {%8,%9}, {%0,%1,%2,%3};\n"
        : "+f"(d[0]), "+f"(d[1]), "+f"(d[2]), "+f"(d[3])
        : "r"(a[0]), "r"(a[1]), "r"(a[2]), "r"(a[3]),
          "r"(b0), "r"(b1));
}

__device__ __forceinline__ void ldsm_x4(uint32_t& r0, uint32_t& r1, uint32_t& r2,
                                        uint32_t& r3, uint32_t addr) {
    asm volatile("ldmatrix.sync.aligned.m8n8.x4.shared.b16 {%0,%1,%2,%3}, [%4];"
                 : "=r"(r0), "=r"(r1), "=r"(r2), "=r"(r3) : "r"(addr));
}

__device__ __forceinline__ void cp_async16(uint32_t saddr, const void* gaddr) {
    asm volatile("cp.async.cg.shared.global [%0], [%1], 16;\n" :: "r"(saddr), "l"(gaddr));
}
__device__ __forceinline__ void cp_commit() { asm volatile("cp.async.commit_group;\n"); }
__device__ __forceinline__ void cp_wait0()  { asm volatile("cp.async.wait_group 0;\n"); }
__device__ __forceinline__ void cp_wait1()  { asm volatile("cp.async.wait_group 1;\n"); }

__device__ __forceinline__ uint32_t smem_u32(const void* p) {
    return (uint32_t)__cvta_generic_to_shared(p);
}

__device__ __forceinline__ uint32_t pack_h2(float x, float y) {
    __half2 hv = __floats2half2_rn(x, y);
    return *(uint32_t*)&hv;
}

// fast gate functions (MUFU-based; err ~1e-6, negligible vs fp16 quantization)
__device__ __forceinline__ float fast_sigmoid(float x) {
    return __fdividef(1.0f, 1.0f + __expf(-x));
}
__device__ __forceinline__ float fast_tanh(float x) {
    return 1.0f - __fdividef(2.0f, __expf(2.0f * x) + 1.0f);
}

// ---------------- init: zero h0 ---------------------------------------------
__global__ void init_state() {
    int i = blockIdx.x * blockDim.x + threadIdx.x;
    if (i < BATCH * HID) g_h[0][i] = __float2half(0.0f);
}

// ---------------- fp32 -> fp16 pre-conversion (once per run) ----------------
__global__ void conv_emb(const float* __restrict__ src) {
    const size_t i = (size_t)blockIdx.x * blockDim.x + threadIdx.x;
    if (i < (size_t)VOCAB * EMB / 8) {
        const float4 a = ((const float4*)src)[2 * i];
        const float4 b = ((const float4*)src)[2 * i + 1];
        uint4 o;
        o.x = pack_h2(a.x, a.y); o.y = pack_h2(a.z, a.w);
        o.z = pack_h2(b.x, b.y); o.w = pack_h2(b.z, b.w);
        ((uint4*)g_emb_h)[i] = o;
    }
}

__global__ void conv_wih(const float* __restrict__ src) {
    const size_t i = (size_t)blockIdx.x * blockDim.x + threadIdx.x;
    if (i < (size_t)GATES * EMB / 8) {
        const float4 a = ((const float4*)src)[2 * i];
        const float4 b = ((const float4*)src)[2 * i + 1];
        uint4 o;
        o.x = pack_h2(a.x, a.y); o.y = pack_h2(a.z, a.w);
        o.z = pack_h2(b.x, b.y); o.w = pack_h2(b.z, b.w);
        ((uint4*)g_wih_h)[i] = o;
    }
}

// ---------------- input projection: ldmatrix + double-buffered cp.async -----
// 128x128 tile, K-chunk 32 halfs. 8 warps (4m x 2n); fragments via ldmatrix
// (stride 20 words: rows tile all 32 banks -> conflict-free). One sync/chunk.
__global__ void __launch_bounds__(256)
input_gemm(const int* __restrict__ x_seq, const float* __restrict__ b_ih,
           const float* __restrict__ b_hh) {
    __shared__ __align__(16) uint32_t sA[2][IG_TILE_W];
    __shared__ __align__(16) uint32_t sB[2][IG_TILE_W];
    __shared__ int stok[128];

    const int tid = threadIdx.x;
    const int bm = blockIdx.y;
    const int bn = blockIdx.x;

    if (tid < 128) stok[tid] = x_seq[bm * 128 + tid];
    __syncthreads();

    const int lane = tid & 31;
    const int w    = tid >> 5;
    const int wm   = w & 3;
    const int wn   = w >> 2;
    const int grp  = lane >> 2;
    const int q4   = lane & 3;

    float acc[2][8][4];
    #pragma unroll
    for (int i = 0; i < 2; i++)
        #pragma unroll
        for (int j = 0; j < 8; j++)
            #pragma unroll
            for (int r = 0; r < 4; r++) acc[i][j][r] = 0.0f;

    // cp.async fill: 128 rows x 4 segs (16B) per tile; 2 items/thread/tile
    const int frow0 = tid >> 2, fseg0 = tid & 3;                 // item 0
    const int frow1 = (tid + 256) >> 2, fseg1 = (tid + 256) & 3; // item 1
    const __half* embRow0 = nullptr;  // resolved per chunk via stok
    auto fill = [&](int c) {
        const int buf = c & 1;
        const int kb = c * 32;
        cp_async16(smem_u32(&sA[buf][frow0 * IG_STRIDE + fseg0 * 4]),
                   g_emb_h + (size_t)stok[frow0] * EMB + kb + fseg0 * 8);
        cp_async16(smem_u32(&sA[buf][frow1 * IG_STRIDE + fseg1 * 4]),
                   g_emb_h + (size_t)stok[frow1] * EMB + kb + fseg1 * 8);
        cp_async16(smem_u32(&sB[buf][frow0 * IG_STRIDE + fseg0 * 4]),
                   g_wih_h + (size_t)(bn * 128 + frow0) * EMB + kb + fseg0 * 8);
        cp_async16(smem_u32(&sB[buf][frow1 * IG_STRIDE + fseg1 * 4]),
                   g_wih_h + (size_t)(bn * 128 + frow1) * EMB + kb + fseg1 * 8);
        cp_commit();
    };

    // ldmatrix lane bases (per buffer)
    uint32_t aL[2], bL[2];
    #pragma unroll
    for (int buf = 0; buf < 2; buf++) {
        aL[buf] = smem_u32(&sA[buf][0]) +
            ((uint32_t)((wm * 32 + (lane & 15)) * IG_STRIDE) + ((lane >> 4) << 2)) * 4;
        bL[buf] = smem_u32(&sB[buf][0]) +
            ((uint32_t)((wn * 64 + (lane & 15)) * IG_STRIDE) + ((lane >> 4) << 2)) * 4;
    }
    const uint32_t ROW16 = 16 * IG_STRIDE * 4;   // byte offset of +16 rows

    fill(0);
    for (int c = 0; c < 16; c++) {
        if (c < 15) { fill(c + 1); cp_wait1(); }
        else        { cp_wait0(); }
        __syncthreads();

        const int buf = c & 1;
        #pragma unroll
        for (int ks = 0; ks < 2; ks++) {
            const uint32_t kB = (uint32_t)ks * 32;
            uint32_t a0[4], a1[4];
            ldsm_x4(a0[0], a0[1], a0[2], a0[3], aL[buf] + kB);
            ldsm_x4(a1[0], a1[1], a1[2], a1[3], aL[buf] + ROW16 + kB);
            #pragma unroll
            for (int pair = 0; pair < 4; pair++) {
                uint32_t w0, w1, w2, w3;
                ldsm_x4(w0, w1, w2, w3, bL[buf] + (uint32_t)pair * ROW16 + kB);
                mma_f16(acc[0][pair * 2],     a0, w0, w2);
                mma_f16(acc[0][pair * 2 + 1], a0, w1, w3);
                mma_f16(acc[1][pair * 2],     a1, w0, w2);
                mma_f16(acc[1][pair * 2 + 1], a1, w1, w3);
            }
        }
        __syncthreads();   // compute done before next fill overwrites buf
    }

    #pragma unroll
    for (int fm = 0; fm < 2; fm++)
        #pragma unroll
        for (int fn = 0; fn < 8; fn++) {
            const int row = bm * 128 + wm * 32 + fm * 16 + grp;
            const int col = bn * 128 + wn * 64 + fn * 8 + q4 * 2;
            const float bi0 = b_ih[col] + b_hh[col];
            const float bi1 = b_ih[col + 1] + b_hh[col + 1];
            float* o0 = g_xgates + (size_t)row * GATES + col;
            o0[0] = acc[fm][fn][0] + bi0;
            o0[1] = acc[fm][fn][1] + bi1;
            float* o1 = g_xgates + (size_t)(row + 8) * GATES + col;
            o1[0] = acc[fm][fn][2] + bi0;
            o1[1] = acc[fm][fn][3] + bi1;
        }
}

// ---------------- persistent recurrence (R10, byte-identical) ---------------
__global__ void __launch_bounds__(NTHREADS, 1)
lstm_persistent(const float* __restrict__ W_hh, float* __restrict__ out) {
    extern __shared__ char smem[];
    const uint32_t smb = smem_u32(smem);
    uint32_t* sW   = (uint32_t*)(smem + SMO_W);
    float*    gbuf = (float*)(smem + SMO_GBUF);   // [2][64][33]

    const int tid  = threadIdx.x;
    const int hj   = blockIdx.x * 8;
    const int lane = tid & 31;
    const int w    = tid >> 5;
    const int wm   = w & 3;          // m base wm*16
    const int kh   = w >> 2;         // K-half: even(0)/odd(1) k-steps
    const int grp  = lane >> 2;
    const int q4   = lane & 3;

    // ---- one-time: W slice (32 x 1024) -> smem fp16 ----
    for (int it = tid; it < 32 * 512; it += NTHREADS) {
        const int n  = it >> 9;
        const int w2 = it & 511;
        const float2 v = *(const float2*)(
            W_hh + (size_t)((n >> 3) * HID + hj + (n & 7)) * HID + w2 * 2);
        sW[n * SW_STRIDE + w2] = pack_h2(v.x, v.y);
    }
    __syncthreads();

    // ldmatrix lane base addresses (bytes)
    const uint32_t aAddrL = smb + SMO_A +
        ((uint32_t)(wm * 16 + (lane & 15)) * SA_STRIDE + ((lane >> 4) << 2)) * 4;
    const uint32_t wAddr0 = smb + SMO_W +
        ((uint32_t)(lane & 15) * SW_STRIDE + ((lane >> 4) << 2)) * 4;
    const uint32_t wAddr1 = wAddr0 + 16 * SW_STRIDE * 4;

    auto fill = [&](const __half* h_in, int c) {
        const int buf = c % 3;
        #pragma unroll
        for (int j = 0; j < 8; j++) {
            const int gi = tid + j * NTHREADS;
            const int b  = gi >> 5;
            const int g  = gi & 31;
            cp_async16(smb + SMO_A + (buf * SA_BUF_W + b * SA_STRIDE + g * 4) * 4,
                       h_in + (size_t)b * HID + c * 256 + g * 8);
        }
        cp_commit();
    };

    // epilogue item indices (fixed per thread)
    const int eb0 = tid >> 3,               ehh0 = tid & 7;
    const int eb1 = (tid + NTHREADS) >> 3,  ehh1 = (tid + NTHREADS) & 7;

    float creg[2] = {0.f, 0.f};            // cell state lives in registers

    for (int t = 0; t < T_SEQ; t++) {
        const __half* __restrict__ h_in  = g_h[t & 1];
        __half* __restrict__       h_out = g_h[(t + 1) & 1];

        float acc[4][4];
        #pragma unroll
        for (int i = 0; i < 4; i++)
            #pragma unroll
            for (int r = 0; r < 4; r++) acc[i][r] = 0.0f;

        fill(h_in, 0);

        // prefetch xgates for this step's epilogue (hide DRAM/L2 latency)
        float xg0[4], xg1[4];
        {
            const float* p0 = g_xgates + ((size_t)t * BATCH + eb0) * GATES + hj + ehh0;
            const float* p1 = g_xgates + ((size_t)t * BATCH + eb1) * GATES + hj + ehh1;
            #pragma unroll
            for (int g = 0; g < 4; g++) {
                xg0[g] = __ldg(p0 + g * HID);
                xg1[g] = __ldg(p1 + g * HID);
            }
        }

        #pragma unroll
        for (int c = 0; c < 4; c++) {
            if (c < 3) { fill(h_in, c + 1); cp_wait1(); }
            else       { cp_wait0(); }
            __syncthreads();

            const uint32_t aBase = aAddrL + (uint32_t)(c % 3) * (SA_BUF_W * 4);
            const uint32_t wOff  = (uint32_t)(c * 16) * 32;   // kw bytes
            #pragma unroll
            for (int ksl2 = 0; ksl2 < 8; ksl2++) {
                const int ksl = ksl2 * 2 + kh;       // interleaved K split
                uint32_t af[4];
                ldsm_x4(af[0], af[1], af[2], af[3], aBase + (uint32_t)ksl * 32);
                uint32_t w00, w01, w02, w03;
                ldsm_x4(w00, w01, w02, w03, wAddr0 + wOff + (uint32_t)ksl * 32);
                mma_f16(acc[0], af, w00, w02);
                mma_f16(acc[1], af, w01, w03);
                uint32_t w10, w11, w12, w13;
                ldsm_x4(w10, w11, w12, w13, wAddr1 + wOff + (uint32_t)ksl * 32);
                mma_f16(acc[2], af, w10, w12);
                mma_f16(acc[3], af, w11, w13);
            }
        }

        // park partial accumulators (per K-half)
        {
            float* gb = gbuf + kh * GBUF_W;
            const int row = wm * 16 + grp;
            #pragma unroll
            for (int fn = 0; fn < 4; fn++) {
                const int col = fn * 8 + q4 * 2;
                gb[row * 33 + col]           = acc[fn][0];
                gb[row * 33 + col + 1]       = acc[fn][1];
                gb[(row + 8) * 33 + col]     = acc[fn][2];
                gb[(row + 8) * 33 + col + 1] = acc[fn][3];
            }
        }
        __syncthreads();

        // fused elementwise: sum the two K-half partials + xg
        float hnew[2];
        #pragma unroll
        for (int it2 = 0; it2 < 2; it2++) {
            const int b    = it2 ? eb1 : eb0;
            const int hh   = it2 ? ehh1 : ehh0;
            const float* xg = it2 ? xg1 : xg0;
            const int hcol = hj + hh;

            const float ip = gbuf[b * 33 + hh]      + gbuf[GBUF_W + b * 33 + hh]      + xg[0];
            const float fp = gbuf[b * 33 + 8 + hh]  + gbuf[GBUF_W + b * 33 + 8 + hh]  + xg[1];
            const float gp = gbuf[b * 33 + 16 + hh] + gbuf[GBUF_W + b * 33 + 16 + hh] + xg[2];
            const float op = gbuf[b * 33 + 24 + hh] + gbuf[GBUF_W + b * 33 + 24 + hh] + xg[3];

            const float ig = fast_sigmoid(ip);
            const float fg = fast_sigmoid(fp);
            const float gg = fast_tanh(gp);
            const float og = fast_sigmoid(op);

            const float c_new = fg * creg[it2] + ig * gg;
            const float h_new = og * fast_tanh(c_new);
            creg[it2] = c_new;
            hnew[it2] = h_new;

            h_out[b * HID + hcol] = __float2half_rn(h_new);
        }

        // ---- grid barrier: single atomic, release early, overlap stores ----
        __syncthreads();                    // all h_out stores done
        unsigned target = 0;
        if (tid == 0) {
            __threadfence();
            unsigned old;
            asm volatile("atom.add.release.gpu.global.u32 %0, [%1], 1;"
                         : "=r"(old) : "l"(&g_bar) : "memory");
            target = old - (old % NCTA) + NCTA;
        }
        // fp32 output stores overlap the barrier poll below
        out[((size_t)t * BATCH + eb0) * HID + hj + ehh0] = hnew[0];
        out[((size_t)t * BATCH + eb1) * HID + hj + ehh1] = hnew[1];
        if (tid == 0) {
            unsigned cur;
            do {
                asm volatile("ld.acquire.gpu.global.u32 %0, [%1];"
                             : "=r"(cur) : "l"(&g_bar) : "memory");
            } while ((int)(cur - target) < 0);
        }
        __syncthreads();
    }

    // final cell state -> global (finalize reads it)
    g_c[eb0 * HID + hj + ehh0] = creg[0];
    g_c[eb1 * HID + hj + ehh1] = creg[1];
}

// ---------------- finalize: append (h, c) after outs ------------------------
__global__ void finalize(float* __restrict__ out) {
    int i = blockIdx.x * blockDim.x + threadIdx.x;
    if (i < BATCH * HID) {
        out[(size_t)T_SEQ * BATCH * HID + i] =
            out[(size_t)(T_SEQ - 1) * BATCH * HID + i];
        out[(size_t)T_SEQ * BATCH * HID + BATCH * HID + i] = g_c[i];
    }
}

// ---------------- launch -----------------------------------------------------
extern "C" void kernel_launch(void* const* d_in, const int* in_sizes, int n_in,
                              void* d_out, int out_size) {
    const int*   x_seq = (const int*)d_in[0];
    const float* emb   = (const float*)d_in[1];
    const float* W_ih  = (const float*)d_in[2];
    const float* W_hh  = (const float*)d_in[3];
    const float* b_ih  = (const float*)d_in[4];
    const float* b_hh  = (const float*)d_in[5];
    float* out = (float*)d_out;

    cudaFuncSetAttribute(lstm_persistent,
                         cudaFuncAttributeMaxDynamicSharedMemorySize, SMEM_BYTES);

    init_state<<<(BATCH * HID + 255) / 256, 256>>>();

    conv_emb<<<(int)(((size_t)VOCAB * EMB / 8 + 255) / 256), 256>>>(emb);
    conv_wih<<<(int)(((size_t)GATES * EMB / 8 + 255) / 256), 256>>>(W_ih);

    dim3 ig_grid(GATES / 128, (T_SEQ * BATCH) / 128);   // (32, 128)
    input_gemm<<<ig_grid, 256>>>(x_seq, b_ih, b_hh);

    lstm_persistent<<<NCTA, NTHREADS, SMEM_BYTES>>>(W_hh, out);

    finalize<<<(BATCH * HID + 255) / 256, 256>>>(out);
}